// round 15
// baseline (speedup 1.0000x reference)
#include <cuda_runtime.h>
#include <cuda_bf16.h>
#include <math.h>
#include <stdint.h>

#define NMAX   20000
#define ETOT_MAX 340000
#define DD     256
#define NGRAPH 16

// ---------------- scratch (static device globals; no allocation) -------------
__device__ float    g_X[NMAX * DD];             // fp32 features (pool reads this)
__device__ __align__(16) unsigned g_Xb[NMAX * 128];   // bf16x2-packed X (GEMM A input)
__device__ __align__(16) unsigned g_Hb[NMAX * 128];   // bf16x2-packed H (gather input)
__device__ __align__(16) unsigned g_W2b[3 * 32768];   // bf16 W2, n-major [l][n][k2]
__device__ float    g_as[NMAX * 4];
__device__ float    g_ad[NMAX * 4];
__device__ int      g_deg[NMAX];                // zero-init; re-zeroed by scan
__device__ int      g_row[NMAX + 1];
__device__ int      g_cur[NMAX];
__device__ int      g_col[ETOT_MAX];
__device__ int      g_eid[ETOT_MAX];
__device__ float    g_gsum[NGRAPH * DD];
__device__ int      g_goff[NGRAPH + 1];
__device__ int      g_is64;
__device__ int      g_done;                     // pool->mlp counter
__device__ int      g_done2;                    // fill completion counter
__device__ int      g_done3;                    // fatt->pool counter
__device__ int      g_tkt;                      // fill ticket counter
__device__ int      g_preDone;                  // pre last-block counter (self-resets)

// ---------------- helpers ----------------------------------------------------
__device__ __forceinline__ float geluf(float x) {
    float t = tanhf(0.7978845608028654f * (x + 0.044715f * x * x * x));
    return 0.5f * x * (1.0f + t);
}
__device__ __forceinline__ float lrelu(float x) { return x > 0.f ? x : 0.2f * x; }

__device__ __forceinline__ long long load_idx(const void* p, long long i) {
    if (g_is64) return ((const long long*)p)[i];
    return (long long)((const int*)p)[i];
}
__device__ __forceinline__ long long load_idx2(const void* p, long long i, int is64) {
    if (is64) return ((const long long*)p)[i];
    return (long long)((const int*)p)[i];
}
__device__ __forceinline__ void mma_bf16(float* c, const unsigned* a, const unsigned* b) {
    asm volatile(
        "mma.sync.aligned.m16n8k16.row.col.f32.bf16.bf16.f32 "
        "{%0,%1,%2,%3},{%4,%5,%6,%7},{%8,%9},{%0,%1,%2,%3};"
        : "+f"(c[0]), "+f"(c[1]), "+f"(c[2]), "+f"(c[3])
        : "r"(a[0]), "r"(a[1]), "r"(a[2]), "r"(a[3]), "r"(b[0]), "r"(b[1]));
}
__device__ __forceinline__ void ldmx4(unsigned* r, uint32_t addr) {
    asm volatile("ldmatrix.sync.aligned.m8n8.x4.shared.b16 {%0,%1,%2,%3}, [%4];"
                 : "=r"(r[0]), "=r"(r[1]), "=r"(r[2]), "=r"(r[3]) : "r"(addr));
}
__device__ __forceinline__ unsigned packbf2(float lo, float hi) {
    __nv_bfloat162 t = __floats2bfloat162_rn(lo, hi);
    return *(unsigned*)&t;
}

// ---- kernel 1 (512 thr): detect+prep1+deg+sd1+bounds+W2pack, then last-block scan
__global__ void __launch_bounds__(512) k_pre(const void* __restrict__ ei,
                                             const float* __restrict__ x,
                                             const void* __restrict__ batch,
                                             const float* __restrict__ W1,
                                             const float* __restrict__ as1,
                                             const float* __restrict__ ad1,
                                             const float* __restrict__ W2,
                                             int E, int Etot, int n) {
    __shared__ int nz;
    __shared__ float ss[256], sd[256];
    __shared__ float scs[4], scd[4];
    __shared__ int slast;
    int tid = threadIdx.x;
    if (tid == 0) nz = 0;
    __syncthreads();
    const int* w32 = (const int*)ei;
    int lim = min(E, 4096);
    for (int j = tid; j < lim; j += 512)
        if (w32[2 * j + 1] != 0) nz = 1;
    if (tid < 256) {
        float w = W1[tid];
        ss[tid] = w * as1[tid];
        sd[tid] = w * ad1[tid];
    }
    __syncthreads();
    int is64 = (nz == 0) ? 1 : 0;
    for (int off = 32; off; off >>= 1) {
        if (tid < 256 && (tid & 63) < off) { ss[tid] += ss[tid + off]; sd[tid] += sd[tid + off]; }
        __syncthreads();
    }
    if (tid < 256 && (tid & 63) == 0) { scs[tid >> 6] = ss[tid]; scd[tid >> 6] = sd[tid]; }
    __syncthreads();

    int e = blockIdx.x * 512 + tid;
    if (e == 0) { g_done = 0; g_done2 = 0; g_done3 = 0; g_tkt = 0; g_is64 = is64; }
    // W2 -> bf16 n-major: g_W2b[l*32768 + n*128 + k2]
    const int nI = 3 * 128 * 64;
    int gstride = gridDim.x * 512;
    for (int idx = e; idx < nI; idx += gstride) {
        int l = idx / 8192, r = idx - l * 8192;
        int k2 = r >> 6, n4 = (r & 63) * 4;
        const float* base = W2 + l * 65536 + (2 * k2) * 256 + n4;
        float4 lo = *(const float4*)base;
        float4 hi = *(const float4*)(base + 256);
        unsigned* dst = g_W2b + l * 32768 + n4 * 128 + k2;
        dst[0]   = packbf2(lo.x, hi.x);
        dst[128] = packbf2(lo.y, hi.y);
        dst[256] = packbf2(lo.z, hi.z);
        dst[384] = packbf2(lo.w, hi.w);
    }
    if (e < Etot) {
        int dst = (e < E) ? (int)load_idx2(ei, (long long)E + e, is64) : (e - E);
        if (dst >= 0 && dst < n) atomicAdd(&g_deg[dst], 1);
    }
    if (e < n) {
        float xv = x[e];
        #pragma unroll
        for (int h = 0; h < 4; h++) {
            g_as[e * 4 + h] = xv * scs[h];
            g_ad[e * 4 + h] = xv * scd[h];
        }
        int b = (int)load_idx2(batch, e, is64);
        int prev = (e == 0) ? -1 : (int)load_idx2(batch, e - 1, is64);
        for (int g = prev + 1; g <= b && g <= NGRAPH; g++)
            if (g >= 0) g_goff[g] = e;
        if (e == n - 1)
            for (int g = b + 1; g <= NGRAPH; g++) g_goff[g] = n;
    }
    // ---- last finishing block runs the prefix scan (no other block waits) ----
    __threadfence();
    __syncthreads();
    if (tid == 0) slast = (atomicAdd(&g_preDone, 1) == gridDim.x - 1) ? 1 : 0;
    __syncthreads();
    if (!slast) return;
    __threadfence();
    __shared__ int sbuf2[5120];
    __shared__ int wsum2[16];
    int lane = tid & 31, w = tid >> 5;         // 16 warps
    int carry = 0;
    #pragma unroll
    for (int ph = 0; ph < 4; ph++) {
        int base = ph * 5120;
        #pragma unroll
        for (int j = 0; j < 10; j++) {
            int idx = base + j * 512 + tid;
            int v = (idx < n) ? g_deg[idx] : 0;
            sbuf2[j * 512 + tid] = v;
            if (idx < n) g_deg[idx] = 0;       // re-zero for next replay
        }
        __syncthreads();
        int vals[10], sum = 0;
        #pragma unroll
        for (int i = 0; i < 10; i++) { vals[i] = sbuf2[tid * 10 + i]; sum += vals[i]; }
        int s = sum;
        #pragma unroll
        for (int off = 1; off < 32; off <<= 1) {
            int v = __shfl_up_sync(0xffffffffu, s, off);
            if (lane >= off) s += v;
        }
        if (lane == 31) wsum2[w] = s;
        __syncthreads();
        if (w == 0) {
            int xx = (lane < 16) ? wsum2[lane] : 0;
            #pragma unroll
            for (int off = 1; off < 16; off <<= 1) {
                int v = __shfl_up_sync(0xffffffffu, xx, off);
                if (lane >= off) xx += v;
            }
            if (lane < 16) wsum2[lane] = xx;
        }
        __syncthreads();
        int excl = s - sum + (w > 0 ? wsum2[w - 1] : 0) + carry;
        int total = wsum2[15];
        __syncthreads();
        int run = excl;
        #pragma unroll
        for (int i = 0; i < 10; i++) { sbuf2[tid * 10 + i] = run; run += vals[i]; }
        __syncthreads();
        #pragma unroll
        for (int j = 0; j < 10; j++) {
            int idx = base + j * 512 + tid;
            if (idx < n) { int v = sbuf2[j * 512 + tid]; g_row[idx] = v; g_cur[idx] = v; }
        }
        carry += total;
        __syncthreads();
    }
    if (tid == 0) { g_row[n] = carry; g_preDone = 0; }
}

// ---- kernel 2: CSR fill (ticket queue) + attn idx + fused layer 1 -----------
__global__ void __launch_bounds__(256) k_fillf1(const void* __restrict__ ei,
                                                int E, int Etot, int n, int NBfill,
                                                float* __restrict__ attn_dst,
                                                const float* __restrict__ x,
                                                const float* __restrict__ W1,
                                                const float* __restrict__ b1) {
    int tid = threadIdx.x;
    __shared__ int schunk;
    int mychunks = 0;
    for (;;) {
        if (tid == 0) schunk = atomicAdd(&g_tkt, 1);
        __syncthreads();
        int chunk = schunk;
        __syncthreads();
        if (chunk >= NBfill) break;
        mychunks++;
        int e = chunk * 256 + tid;
        if (e < Etot) {
            int src, dst;
            if (e < E) {
                src = (int)load_idx(ei, e);
                dst = (int)load_idx(ei, (long long)E + e);
            } else { src = e - E; dst = e - E; }
            if (attn_dst) {
                attn_dst[e] = (float)src;
                attn_dst[Etot + e] = (float)dst;
            }
            if (dst >= 0 && dst < n && src >= 0 && src < n) {
                int pos = atomicAdd(&g_cur[dst], 1);
                g_col[pos] = src;
                g_eid[pos] = e;
            }
        }
    }
    __threadfence();
    __syncthreads();
    if (tid == 0) {
        if (mychunks) atomicAdd(&g_done2, mychunks);
        while (atomicAdd(&g_done2, 0) < NBfill) __nanosleep(100);
    }
    __syncthreads();
    __threadfence();
    // ---- phase 2: fused layer 1 ----
    int wid = tid >> 5, lane = tid & 31;
    int d = blockIdx.x * 8 + wid;
    if (d >= n) return;
    int b = g_row[d], e2 = g_row[d + 1];
    float4 ad = ((const float4*)g_ad)[d];
    const int NC = 4;
    float4 ev[NC]; float xv[NC];
    float4 mx = make_float4(-1e30f, -1e30f, -1e30f, -1e30f);
    int i = 0;
    for (int p = b + lane; p < e2; p += 32, i++) {
        int c = g_col[p];
        float4 av = ((const float4*)g_as)[c];
        float4 v;
        v.x = lrelu(av.x + ad.x); v.y = lrelu(av.y + ad.y);
        v.z = lrelu(av.z + ad.z); v.w = lrelu(av.w + ad.w);
        float xx = x[c];
        if (i < NC) { ev[i] = v; xv[i] = xx; }
        mx.x = fmaxf(mx.x, v.x); mx.y = fmaxf(mx.y, v.y);
        mx.z = fmaxf(mx.z, v.z); mx.w = fmaxf(mx.w, v.w);
    }
    #pragma unroll
    for (int o = 16; o; o >>= 1) {
        mx.x = fmaxf(mx.x, __shfl_xor_sync(0xffffffffu, mx.x, o));
        mx.y = fmaxf(mx.y, __shfl_xor_sync(0xffffffffu, mx.y, o));
        mx.z = fmaxf(mx.z, __shfl_xor_sync(0xffffffffu, mx.z, o));
        mx.w = fmaxf(mx.w, __shfl_xor_sync(0xffffffffu, mx.w, o));
    }
    float4 sm = make_float4(0, 0, 0, 0);
    i = 0;
    for (int p = b + lane; p < e2; p += 32, i++) {
        float4 v;
        if (i < NC) v = ev[i];
        else {
            int c = g_col[p];
            float4 av = ((const float4*)g_as)[c];
            v.x = lrelu(av.x + ad.x); v.y = lrelu(av.y + ad.y);
            v.z = lrelu(av.z + ad.z); v.w = lrelu(av.w + ad.w);
        }
        v.x = expf(v.x - mx.x); v.y = expf(v.y - mx.y);
        v.z = expf(v.z - mx.z); v.w = expf(v.w - mx.w);
        if (i < NC) ev[i] = v;
        sm.x += v.x; sm.y += v.y; sm.z += v.z; sm.w += v.w;
    }
    #pragma unroll
    for (int o = 16; o; o >>= 1) {
        sm.x += __shfl_xor_sync(0xffffffffu, sm.x, o);
        sm.y += __shfl_xor_sync(0xffffffffu, sm.y, o);
        sm.z += __shfl_xor_sync(0xffffffffu, sm.z, o);
        sm.w += __shfl_xor_sync(0xffffffffu, sm.w, o);
    }
    float4 inv;
    inv.x = 1.f / (sm.x + 1e-16f); inv.y = 1.f / (sm.y + 1e-16f);
    inv.z = 1.f / (sm.z + 1e-16f); inv.w = 1.f / (sm.w + 1e-16f);
    float4 acc = make_float4(0, 0, 0, 0);
    i = 0;
    for (int p = b + lane; p < e2; p += 32, i++) {
        float4 al; float xx;
        if (i < NC) { al = ev[i]; xx = xv[i]; }
        else {
            int c = g_col[p];
            float4 av = ((const float4*)g_as)[c];
            al.x = expf(lrelu(av.x + ad.x) - mx.x);
            al.y = expf(lrelu(av.y + ad.y) - mx.y);
            al.z = expf(lrelu(av.z + ad.z) - mx.z);
            al.w = expf(lrelu(av.w + ad.w) - mx.w);
            xx = x[c];
        }
        acc.x += al.x * inv.x * xx; acc.y += al.y * inv.y * xx;
        acc.z += al.z * inv.z * xx; acc.w += al.w * inv.w * xx;
    }
    #pragma unroll
    for (int o = 16; o; o >>= 1) {
        acc.x += __shfl_xor_sync(0xffffffffu, acc.x, o);
        acc.y += __shfl_xor_sync(0xffffffffu, acc.y, o);
        acc.z += __shfl_xor_sync(0xffffffffu, acc.z, o);
        acc.w += __shfl_xor_sync(0xffffffffu, acc.w, o);
    }
    int head = lane >> 3;
    float hv = (head == 0) ? acc.x : (head == 1) ? acc.y : (head == 2) ? acc.z : acc.w;
    int c0 = lane * 8;
    const float4* wp = (const float4*)&W1[c0];
    const float4* bp = (const float4*)&b1[c0];
    float4 w0 = wp[0], w1 = wp[1], bb0 = bp[0], bb1 = bp[1];
    float4 o0, o1;
    o0.x = geluf(hv * w0.x + bb0.x); o0.y = geluf(hv * w0.y + bb0.y);
    o0.z = geluf(hv * w0.z + bb0.z); o0.w = geluf(hv * w0.w + bb0.w);
    o1.x = geluf(hv * w1.x + bb1.x); o1.y = geluf(hv * w1.y + bb1.y);
    o1.z = geluf(hv * w1.z + bb1.z); o1.w = geluf(hv * w1.w + bb1.w);
    float4* xp = (float4*)&g_X[d * 256 + c0];
    xp[0] = o0; xp[1] = o1;
    uint4 xb;
    xb.x = packbf2(o0.x, o0.y); xb.y = packbf2(o0.z, o0.w);
    xb.z = packbf2(o1.x, o1.y); xb.w = packbf2(o1.z, o1.w);
    ((uint4*)&g_Xb[d * 128])[lane] = xb;
}

// ---- bf16 TC GEMM (m16n8k16) with ldmatrix fragments ------------------------
// dyn smem (words): A [2][128][20] + B [2][64][20] = 7680 words = 30720 bytes
#define ASTW  2560
#define BOFFW 5120
#define BSTW  1280
__global__ void __launch_bounds__(256, 4) k_gemm(int l,
                                                 const float* __restrict__ att_s,
                                                 const float* __restrict__ att_d, int M) {
    extern __shared__ unsigned smw[];
    __shared__ float s_pas[128], s_pad[128];
    uint32_t sbase;
    asm("{ .reg .u64 t; cvta.to.shared.u64 t, %1; cvt.u32.u64 %0, t; }"
        : "=r"(sbase) : "l"(smw));
    const unsigned* Wb = g_W2b + l * 32768;   // n-major: [n][k2], 128 words/row
    int tid = threadIdx.x;
    int lane = tid & 31;
    int wid = tid >> 5;
    int wm = (wid & 3) * 32;
    int wng = wid >> 2;
    int wn = wng * 32;
    int m0 = blockIdx.x * 128;
    int n0 = blockIdx.y * 64;

    float acc[2][4][4];
    #pragma unroll
    for (int mi = 0; mi < 2; mi++)
        #pragma unroll
        for (int ni = 0; ni < 4; ni++)
            #pragma unroll
            for (int q = 0; q < 4; q++) acc[mi][ni][q] = 0.f;

    auto load_stage = [&](int s, int k0w) {
        #pragma unroll
        for (int i = 0; i < 2; i++) {
            int g = tid + i * 256;
            int m = g >> 2, kq = (g & 3) * 4;
            int gm = m0 + m;
            const unsigned* src = &g_Xb[(long long)((gm < M) ? gm : 0) * 128 + k0w + kq];
            uint32_t dst = sbase + (s * ASTW + m * 20 + kq) * 4;
            int sz = (gm < M) ? 16 : 0;
            asm volatile("cp.async.cg.shared.global [%0],[%1],16,%2;"
                         :: "r"(dst), "l"(src), "r"(sz));
        }
        {
            int nn = tid >> 2, kq = (tid & 3) * 4;
            const unsigned* src = &Wb[(n0 + nn) * 128 + k0w + kq];
            uint32_t dst = sbase + (BOFFW + s * BSTW + nn * 20 + kq) * 4;
            asm volatile("cp.async.cg.shared.global [%0],[%1],16,%2;"
                         :: "r"(dst), "l"(src), "r"(16));
        }
        asm volatile("cp.async.commit_group;");
    };

    load_stage(0, 0);
    int c4 = lane & 3, r8 = lane >> 2;
    int grp = lane >> 3, l8 = lane & 7;
    int aRow = wm + (grp & 1) * 8 + l8;
    int aWrd = (grp >> 1) * 4;
    int bRow = wn + (grp >> 1) * 8 + l8;
    int bWrd = (grp & 1) * 4;

    for (int it = 0; it < 8; it++) {
        int s = it & 1;
        asm volatile("cp.async.wait_group 0;");
        __syncthreads();
        if (it < 7) load_stage((it + 1) & 1, (it + 1) * 16);
        #pragma unroll
        for (int ks = 0; ks < 2; ks++) {
            int kw = ks * 8;
            unsigned a[2][4], bf[4][2];
            #pragma unroll
            for (int mi = 0; mi < 2; mi++) {
                uint32_t addr = sbase + (s * ASTW + (aRow + mi * 16) * 20 + kw + aWrd) * 4;
                ldmx4(a[mi], addr);
            }
            #pragma unroll
            for (int nip = 0; nip < 2; nip++) {
                unsigned q[4];
                uint32_t addr = sbase + (BOFFW + s * BSTW + (bRow + nip * 16) * 20 + kw + bWrd) * 4;
                ldmx4(q, addr);
                bf[2 * nip][0] = q[0]; bf[2 * nip][1] = q[1];
                bf[2 * nip + 1][0] = q[2]; bf[2 * nip + 1][1] = q[3];
            }
            #pragma unroll
            for (int mi = 0; mi < 2; mi++)
                #pragma unroll
                for (int ni = 0; ni < 4; ni++)
                    mma_bf16(acc[mi][ni], a[mi], bf[ni]);
        }
    }
    float pas[4] = {0, 0, 0, 0}, pad_[4] = {0, 0, 0, 0};
    #pragma unroll
    for (int mi = 0; mi < 2; mi++) {
        int m = m0 + wm + mi * 16 + r8;
        #pragma unroll
        for (int ni = 0; ni < 4; ni++) {
            int nn = n0 + wn + ni * 8 + 2 * c4;
            float s0 = __ldg(&att_s[nn]), s1 = __ldg(&att_s[nn + 1]);
            float d0 = __ldg(&att_d[nn]), d1 = __ldg(&att_d[nn + 1]);
            pas[2 * mi]     += acc[mi][ni][0] * s0 + acc[mi][ni][1] * s1;
            pas[2 * mi + 1] += acc[mi][ni][2] * s0 + acc[mi][ni][3] * s1;
            pad_[2 * mi]     += acc[mi][ni][0] * d0 + acc[mi][ni][1] * d1;
            pad_[2 * mi + 1] += acc[mi][ni][2] * d0 + acc[mi][ni][3] * d1;
            if (m < M)
                g_Hb[m * 128 + (nn >> 1)] = packbf2(acc[mi][ni][0], acc[mi][ni][1]);
            if (m + 8 < M)
                g_Hb[(m + 8) * 128 + (nn >> 1)] = packbf2(acc[mi][ni][2], acc[mi][ni][3]);
        }
    }
    #pragma unroll
    for (int off = 1; off < 4; off <<= 1) {
        #pragma unroll
        for (int r = 0; r < 4; r++) {
            pas[r]  += __shfl_xor_sync(0xffffffffu, pas[r], off);
            pad_[r] += __shfl_xor_sync(0xffffffffu, pad_[r], off);
        }
    }
    if (c4 == 0 && wng == 1) {
        #pragma unroll
        for (int r = 0; r < 4; r++) {
            int row = wm + r8 + (r & 1) * 8 + (r >> 1) * 16;
            s_pas[row] = pas[r]; s_pad[row] = pad_[r];
        }
    }
    __syncthreads();
    if (c4 == 0 && wng == 0) {
        #pragma unroll
        for (int r = 0; r < 4; r++) {
            int row = wm + r8 + (r & 1) * 8 + (r >> 1) * 16;
            int m = m0 + row;
            if (m < M) {
                g_as[m * 4 + blockIdx.y] = pas[r] + s_pas[row];
                g_ad[m * 4 + blockIdx.y] = pad_[r] + s_pad[row];
            }
        }
    }
}

// ---- fatt device body (softmax + gather + gelu for one dst) -----------------
__device__ __forceinline__ void fatt_body(int d, const float* __restrict__ bias,
                                          float* __restrict__ alpha_out,
                                          int writeXb, int lane) {
    int b = g_row[d], e = g_row[d + 1];
    float4 dv = ((const float4*)g_ad)[d];
    float ad = (dv.x + dv.y) + (dv.z + dv.w);
    const int NC = 8;
    float ev[NC]; int col[NC];
    float mx = -1e30f;
    int i = 0;
    for (int p = b + lane; p < e; p += 32, i++) {
        int c = g_col[p];
        float4 sv = ((const float4*)g_as)[c];
        float v = lrelu((sv.x + sv.y) + (sv.z + sv.w) + ad);
        if (i < NC) { ev[i] = v; col[i] = c; }
        mx = fmaxf(mx, v);
    }
    #pragma unroll
    for (int o = 16; o; o >>= 1) mx = fmaxf(mx, __shfl_xor_sync(0xffffffffu, mx, o));
    float sm = 0.f;
    i = 0;
    for (int p = b + lane; p < e; p += 32, i++) {
        float v;
        if (i < NC) v = ev[i];
        else {
            float4 sv = ((const float4*)g_as)[g_col[p]];
            v = lrelu((sv.x + sv.y) + (sv.z + sv.w) + ad);
        }
        v = expf(v - mx);
        if (i < NC) ev[i] = v;
        sm += v;
    }
    #pragma unroll
    for (int o = 16; o; o >>= 1) sm += __shfl_xor_sync(0xffffffffu, sm, o);
    float inv = 1.f / (sm + 1e-16f);

    float acc[8];
    #pragma unroll
    for (int j = 0; j < 8; j++) acc[j] = 0.f;
    for (int base = b; base < e; base += 32) {
        int p = base + lane;
        int idx = (base - b) >> 5;
        float aa = 0.f; int cc = 0;
        if (p < e) {
            if (idx < NC) { aa = ev[idx] * inv; cc = col[idx]; }
            else {
                cc = g_col[p];
                float4 sv = ((const float4*)g_as)[cc];
                aa = expf(lrelu((sv.x + sv.y) + (sv.z + sv.w) + ad) - mx) * inv;
            }
            if (alpha_out) alpha_out[g_eid[p]] = aa;
        }
        int lim = min(32, e - base);
        #pragma unroll 8
        for (int t = 0; t < lim; t++) {
            int   c = __shfl_sync(0xffffffffu, cc, t);
            float a = __shfl_sync(0xffffffffu, aa, t);
            uint4 v = ((const uint4*)&g_Hb[c * 128])[lane];
            float2 f0 = __bfloat1622float2(*(__nv_bfloat162*)&v.x);
            float2 f1 = __bfloat1622float2(*(__nv_bfloat162*)&v.y);
            float2 f2 = __bfloat1622float2(*(__nv_bfloat162*)&v.z);
            float2 f3 = __bfloat1622float2(*(__nv_bfloat162*)&v.w);
            acc[0] += a * f0.x; acc[1] += a * f0.y;
            acc[2] += a * f1.x; acc[3] += a * f1.y;
            acc[4] += a * f2.x; acc[5] += a * f2.y;
            acc[6] += a * f3.x; acc[7] += a * f3.y;
        }
    }
    float4 o0, o1;
    const float4* bv = (const float4*)&bias[lane * 8];
    float4 b0 = bv[0], b1 = bv[1];
    o0.x = geluf(acc[0] + b0.x); o0.y = geluf(acc[1] + b0.y);
    o0.z = geluf(acc[2] + b0.z); o0.w = geluf(acc[3] + b0.w);
    o1.x = geluf(acc[4] + b1.x); o1.y = geluf(acc[5] + b1.y);
    o1.z = geluf(acc[6] + b1.z); o1.w = geluf(acc[7] + b1.w);
    float4* xp = (float4*)&g_X[d * 256 + lane * 8];
    xp[0] = o0; xp[1] = o1;
    if (writeXb) {
        uint4 xb;
        xb.x = packbf2(o0.x, o0.y); xb.y = packbf2(o0.z, o0.w);
        xb.z = packbf2(o1.x, o1.y); xb.w = packbf2(o1.z, o1.w);
        ((uint4*)&g_Xb[d * 128])[lane] = xb;
    }
}

// ------- fused edge softmax + aggregation (layers 2,3), warp per dst ---------
__global__ void __launch_bounds__(256) k_fatt(const float* __restrict__ bias, int n) {
    int wid = threadIdx.x >> 5, lane = threadIdx.x & 31;
    int d = blockIdx.x * 8 + wid;
    if (d >= n) return;
    fatt_body(d, bias, nullptr, 1, lane);
}

// ------- last layer: fatt + alpha out + pool (blocks 0-15) + MLP (block 16) --
__global__ void __launch_bounds__(256, 4) k_fattpool(const float* __restrict__ bias, int n,
                                                     float* __restrict__ alpha_out,
                                                     const float* __restrict__ Wl1, const float* __restrict__ bl1,
                                                     const float* __restrict__ Wl2, const float* __restrict__ bl2,
                                                     const float* __restrict__ Wl3, const float* __restrict__ bl3,
                                                     float* __restrict__ out) {
    int tid = threadIdx.x;
    int wid = tid >> 5, lane = tid & 31;
    int d = blockIdx.x * 8 + wid;
    if (d < n) fatt_body(d, bias, alpha_out, 0, lane);
    // barrier: count every block
    __threadfence();
    __syncthreads();
    if (tid == 0) atomicAdd(&g_done3, 1);
    if (blockIdx.x >= NGRAPH + 1) return;
    if (tid == 0) {
        while (atomicAdd(&g_done3, 0) < gridDim.x) __nanosleep(100);
    }
    __syncthreads();
    __threadfence();
    if (blockIdx.x < NGRAPH) {
        // pool graph blockIdx.x (256 threads, 4 row-groups)
        __shared__ float sbuf[4][256];
        int g = blockIdx.x;
        int s = tid >> 6, c4 = tid & 63;
        int b = g_goff[g], e = g_goff[g + 1];
        float4 acc = make_float4(0, 0, 0, 0);
        for (int i = b + s; i < e; i += 4) {
            float4 v = *(const float4*)&g_X[i * 256 + c4 * 4];
            acc.x += v.x; acc.y += v.y; acc.z += v.z; acc.w += v.w;
        }
        *(float4*)&sbuf[s][c4 * 4] = acc;
        __syncthreads();
        if (s == 0) {
            #pragma unroll
            for (int k = 0; k < 4; k++) {
                int c = c4 * 4 + k;
                g_gsum[g * 256 + c] = sbuf[0][c] + sbuf[1][c] + sbuf[2][c] + sbuf[3][c];
            }
        }
        __threadfence();
        __syncthreads();
        if (tid == 0) atomicAdd(&g_done, 1);
        return;
    }
    // MLP block (blockIdx == NGRAPH), 256 threads
    if (tid == 0) {
        while (atomicAdd(&g_done, 0) < NGRAPH) __nanosleep(100);
    }
    __syncthreads();
    __threadfence();
    __shared__ float G[16 * 256];
    __shared__ float G1[16 * 128];
    __shared__ float G2[16 * 64];
    for (int i = tid; i < 4096; i += 256) {
        int g = i >> 8;
        int cnt = g_goff[g + 1] - g_goff[g];
        G[i] = g_gsum[i] / (float)(cnt > 0 ? cnt : 1);
    }
    __syncthreads();
    for (int i = tid; i < 2048; i += 256) {
        int gi = i >> 7, j = i & 127;
        float a = bl1[j];
        for (int k = 0; k < 256; k++) a += G[gi * 256 + k] * Wl1[k * 128 + j];
        G1[i] = geluf(a);
    }
    __syncthreads();
    for (int i = tid; i < 1024; i += 256) {
        int gi = i >> 6, j = i & 63;
        float a = bl2[j];
        for (int k = 0; k < 128; k++) a += G1[gi * 128 + k] * Wl2[k * 64 + j];
        G2[i] = geluf(a);
    }
    __syncthreads();
    if (tid < 16) {
        float a = bl3[0];
        for (int k = 0; k < 64; k++) a += G2[tid * 64 + k] * Wl3[k];
        out[tid] = 1.f / (1.f + expf(-a));
    }
}

// ---------------- host launcher ------------------------------------------------
extern "C" void kernel_launch(void* const* d_in, const int* in_sizes, int n_in,
                              void* d_out, int out_size) {
    const float* x     = (const float*)d_in[0];
    const void*  ei    = d_in[1];
    const void*  batch = d_in[2];
    const float* W1  = (const float*)d_in[3];
    const float* as1 = (const float*)d_in[4];
    const float* ad1 = (const float*)d_in[5];
    const float* b1  = (const float*)d_in[6];
    const float* W2  = (const float*)d_in[7];
    const float* as2 = (const float*)d_in[8];
    const float* ad2 = (const float*)d_in[9];
    const float* b2  = (const float*)d_in[10];
    const float* Wl1 = (const float*)d_in[11];
    const float* bl1 = (const float*)d_in[12];
    const float* Wl2 = (const float*)d_in[13];
    const float* bl2 = (const float*)d_in[14];
    const float* Wl3 = (const float*)d_in[15];
    const float* bl3 = (const float*)d_in[16];

    int Nn = in_sizes[0];
    int E = in_sizes[1] / 2;
    int Etot = E + Nn;
    float* out = (float*)d_out;
    bool full = (out_size >= 16 + 3 * Etot);
    float* attn_out  = full ? (out + 16) : nullptr;
    float* alpha_out = full ? (out + 16 + 2 * Etot) : nullptr;

    int NBfill = (Etot + 255) / 256;
    int NBf1   = (Nn + 7) / 8;
    int NBgrid = (NBf1 > NBfill) ? NBf1 : NBfill;

    cudaFuncSetAttribute(k_gemm, cudaFuncAttributeMaxDynamicSharedMemorySize, 30720);

    // 1: detect + prep1 + deg count + sd1 + bounds + W2 pack + inline scan
    k_pre<<<(Etot + 511) / 512, 512>>>(ei, x, batch, W1, as1, ad1, W2, E, Etot, Nn);
    // 2: CSR fill + attn idx + fused layer 1
    k_fillf1<<<NBgrid, 256>>>(ei, E, Etot, Nn, NBfill, attn_out, x, W1, b1);
    // 3-8: layers 2-4 (last fatt carries pool + MLP)
    for (int l = 0; l < 3; l++) {
        k_gemm<<<dim3((Nn + 127) / 128, 4), 256, 30720>>>(l, as2 + l * 256,
                                                          ad2 + l * 256, Nn);
        if (l < 2)
            k_fatt<<<(Nn + 7) / 8, 256>>>(b2 + l * 256, Nn);
        else
            k_fattpool<<<(Nn + 7) / 8, 256>>>(b2 + l * 256, Nn, alpha_out,
                                              Wl1, bl1, Wl2, bl2, Wl3, bl3, out);
    }
}

// round 16
// speedup vs baseline: 1.1386x; 1.1386x over previous
#include <cuda_runtime.h>
#include <cuda_bf16.h>
#include <math.h>
#include <stdint.h>

#define NMAX   20000
#define ETOT_MAX 340000
#define DD     256
#define NGRAPH 16

// ---------------- scratch (static device globals; no allocation) -------------
__device__ float    g_X[NMAX * DD];             // fp32 features (pool reads this)
__device__ __align__(16) unsigned g_Xb[NMAX * 128];   // bf16x2-packed X (GEMM A input)
__device__ __align__(16) unsigned g_Hb[NMAX * 128];   // bf16x2-packed H (gather input)
__device__ __align__(16) unsigned g_W2b[3 * 32768];   // bf16 W2, n-major [l][n][k2]
__device__ float    g_as[NMAX * 4];
__device__ float    g_ad[NMAX * 4];
__device__ int      g_deg[NMAX];                // zero-init; re-zeroed by k_scan
__device__ int      g_row[NMAX + 1];
__device__ int      g_cur[NMAX];
__device__ int      g_col[ETOT_MAX];
__device__ int      g_eid[ETOT_MAX];
__device__ float    g_gsum[NGRAPH * DD];
__device__ int      g_goff[NGRAPH + 1];
__device__ int      g_is64;
__device__ int      g_done;
__device__ int      g_done2;
__device__ int      g_tkt;

// ---------------- helpers ----------------------------------------------------
__device__ __forceinline__ float geluf(float x) {
    float t = tanhf(0.7978845608028654f * (x + 0.044715f * x * x * x));
    return 0.5f * x * (1.0f + t);
}
__device__ __forceinline__ float lrelu(float x) { return x > 0.f ? x : 0.2f * x; }

__device__ __forceinline__ long long load_idx(const void* p, long long i) {
    if (g_is64) return ((const long long*)p)[i];
    return (long long)((const int*)p)[i];
}
__device__ __forceinline__ long long load_idx2(const void* p, long long i, int is64) {
    if (is64) return ((const long long*)p)[i];
    return (long long)((const int*)p)[i];
}
__device__ __forceinline__ void mma_bf16(float* c, const unsigned* a, const unsigned* b) {
    asm volatile(
        "mma.sync.aligned.m16n8k16.row.col.f32.bf16.bf16.f32 "
        "{%0,%1,%2,%3},{%4,%5,%6,%7},{%8,%9},{%0,%1,%2,%3};"
        : "+f"(c[0]), "+f"(c[1]), "+f"(c[2]), "+f"(c[3])
        : "r"(a[0]), "r"(a[1]), "r"(a[2]), "r"(a[3]), "r"(b[0]), "r"(b[1]));
}
__device__ __forceinline__ void ldmx4(unsigned* r, uint32_t addr) {
    asm volatile("ldmatrix.sync.aligned.m8n8.x4.shared.b16 {%0,%1,%2,%3}, [%4];"
                 : "=r"(r[0]), "=r"(r[1]), "=r"(r[2]), "=r"(r[3]) : "r"(addr));
}
__device__ __forceinline__ unsigned packbf2(float lo, float hi) {
    __nv_bfloat162 t = __floats2bfloat162_rn(lo, hi);
    return *(unsigned*)&t;
}
// f32x2 packed fma: acc += d * ap (element-wise on register pairs)
__device__ __forceinline__ void ffma2(unsigned long long& acc, unsigned lo, unsigned hi,
                                      unsigned long long ap) {
    unsigned long long d;
    asm("mov.b64 %0, {%1,%2};" : "=l"(d) : "r"(lo), "r"(hi));
    asm("fma.rn.f32x2 %0, %1, %2, %0;" : "+l"(acc) : "l"(d), "l"(ap));
}

// ---- kernel 1: detect + prep1 + deg count + sd1 + bounds + W2->bf16 ---------
__global__ void __launch_bounds__(256) k_pre(const void* __restrict__ ei,
                                             const float* __restrict__ x,
                                             const void* __restrict__ batch,
                                             const float* __restrict__ W1,
                                             const float* __restrict__ as1,
                                             const float* __restrict__ ad1,
                                             const float* __restrict__ W2,
                                             int E, int Etot, int n) {
    __shared__ int nz;
    __shared__ float ss[256], sd[256];
    __shared__ float scs[4], scd[4];
    int tid = threadIdx.x;
    if (tid == 0) nz = 0;
    __syncthreads();
    const int* w32 = (const int*)ei;
    int lim = min(E, 4096);
    for (int j = tid; j < lim; j += 256)
        if (w32[2 * j + 1] != 0) nz = 1;
    float w = W1[tid];
    ss[tid] = w * as1[tid];
    sd[tid] = w * ad1[tid];
    __syncthreads();
    int is64 = (nz == 0) ? 1 : 0;
    for (int off = 32; off; off >>= 1) {
        if ((tid & 63) < off) { ss[tid] += ss[tid + off]; sd[tid] += sd[tid + off]; }
        __syncthreads();
    }
    if ((tid & 63) == 0) { scs[tid >> 6] = ss[tid]; scd[tid >> 6] = sd[tid]; }
    __syncthreads();

    int e = blockIdx.x * 256 + tid;
    if (e == 0) { g_done = 0; g_done2 = 0; g_tkt = 0; g_is64 = is64; }
    // W2 -> bf16 n-major: g_W2b[l*32768 + n*128 + k2]
    const int nI = 3 * 128 * 64;
    int gstride = gridDim.x * 256;
    for (int idx = e; idx < nI; idx += gstride) {
        int l = idx / 8192, r = idx - l * 8192;
        int k2 = r >> 6, n4 = (r & 63) * 4;
        const float* base = W2 + l * 65536 + (2 * k2) * 256 + n4;
        float4 lo = *(const float4*)base;
        float4 hi = *(const float4*)(base + 256);
        unsigned* dst = g_W2b + l * 32768 + n4 * 128 + k2;
        dst[0]   = packbf2(lo.x, hi.x);
        dst[128] = packbf2(lo.y, hi.y);
        dst[256] = packbf2(lo.z, hi.z);
        dst[384] = packbf2(lo.w, hi.w);
    }
    if (e < Etot) {
        int dst = (e < E) ? (int)load_idx2(ei, (long long)E + e, is64) : (e - E);
        if (dst >= 0 && dst < n) atomicAdd(&g_deg[dst], 1);
    }
    if (e < n) {
        float xv = x[e];
        #pragma unroll
        for (int h = 0; h < 4; h++) {
            g_as[e * 4 + h] = xv * scs[h];
            g_ad[e * 4 + h] = xv * scd[h];
        }
        int b = (int)load_idx2(batch, e, is64);
        int prev = (e == 0) ? -1 : (int)load_idx2(batch, e - 1, is64);
        for (int g = prev + 1; g <= b && g <= NGRAPH; g++)
            if (g >= 0) g_goff[g] = e;
        if (e == n - 1)
            for (int g = b + 1; g <= NGRAPH; g++) g_goff[g] = n;
    }
}

// ---- kernel 2: coalesced two-phase scan (self-cleans g_deg) ------------------
__global__ void __launch_bounds__(1024) k_scan(int n) {
    __shared__ int sbuf[10240];
    __shared__ int wsum[32];
    int t = threadIdx.x, lane = t & 31, w = t >> 5;
    int carry = 0;
    #pragma unroll
    for (int ph = 0; ph < 2; ph++) {
        int base = ph * 10240;
        #pragma unroll
        for (int j = 0; j < 10; j++) {
            int idx = base + j * 1024 + t;
            int v = (idx < n) ? g_deg[idx] : 0;
            sbuf[j * 1024 + t] = v;
            if (idx < n) g_deg[idx] = 0;
        }
        __syncthreads();
        int vals[10], sum = 0;
        #pragma unroll
        for (int i = 0; i < 10; i++) { vals[i] = sbuf[t * 10 + i]; sum += vals[i]; }
        int s = sum;
        #pragma unroll
        for (int off = 1; off < 32; off <<= 1) {
            int v = __shfl_up_sync(0xffffffffu, s, off);
            if (lane >= off) s += v;
        }
        if (lane == 31) wsum[w] = s;
        __syncthreads();
        if (w == 0) {
            int x = wsum[lane];
            #pragma unroll
            for (int off = 1; off < 32; off <<= 1) {
                int v = __shfl_up_sync(0xffffffffu, x, off);
                if (lane >= off) x += v;
            }
            wsum[lane] = x;
        }
        __syncthreads();
        int excl = s - sum + (w > 0 ? wsum[w - 1] : 0) + carry;
        int total = wsum[31];
        __syncthreads();
        int run = excl;
        #pragma unroll
        for (int i = 0; i < 10; i++) { sbuf[t * 10 + i] = run; run += vals[i]; }
        __syncthreads();
        #pragma unroll
        for (int j = 0; j < 10; j++) {
            int idx = base + j * 1024 + t;
            if (idx < n) { int v = sbuf[j * 1024 + t]; g_row[idx] = v; g_cur[idx] = v; }
        }
        carry += total;
        __syncthreads();
    }
    if (t == 0) g_row[n] = carry;
}

// ---- kernel 3: CSR fill (ticket queue) + attn idx + fused layer 1 -----------
__global__ void __launch_bounds__(256) k_fillf1(const void* __restrict__ ei,
                                                int E, int Etot, int n, int NBfill,
                                                float* __restrict__ attn_dst,
                                                const float* __restrict__ x,
                                                const float* __restrict__ W1,
                                                const float* __restrict__ b1) {
    int tid = threadIdx.x;
    __shared__ int schunk;
    int mychunks = 0;
    for (;;) {
        if (tid == 0) schunk = atomicAdd(&g_tkt, 1);
        __syncthreads();
        int chunk = schunk;
        __syncthreads();
        if (chunk >= NBfill) break;
        mychunks++;
        int e = chunk * 256 + tid;
        if (e < Etot) {
            int src, dst;
            if (e < E) {
                src = (int)load_idx(ei, e);
                dst = (int)load_idx(ei, (long long)E + e);
            } else { src = e - E; dst = e - E; }
            if (attn_dst) {
                attn_dst[e] = (float)src;
                attn_dst[Etot + e] = (float)dst;
            }
            if (dst >= 0 && dst < n && src >= 0 && src < n) {
                int pos = atomicAdd(&g_cur[dst], 1);
                g_col[pos] = src;
                g_eid[pos] = e;
            }
        }
    }
    __threadfence();
    __syncthreads();
    if (tid == 0) {
        if (mychunks) atomicAdd(&g_done2, mychunks);
        while (atomicAdd(&g_done2, 0) < NBfill) __nanosleep(100);
    }
    __syncthreads();
    __threadfence();
    // ---- phase 2: fused layer 1 ----
    int wid = tid >> 5, lane = tid & 31;
    int d = blockIdx.x * 8 + wid;
    if (d >= n) return;
    int b = g_row[d], e2 = g_row[d + 1];
    float4 ad = ((const float4*)g_ad)[d];
    const int NC = 4;
    float4 ev[NC]; float xv[NC];
    float4 mx = make_float4(-1e30f, -1e30f, -1e30f, -1e30f);
    int i = 0;
    for (int p = b + lane; p < e2; p += 32, i++) {
        int c = g_col[p];
        float4 av = ((const float4*)g_as)[c];
        float4 v;
        v.x = lrelu(av.x + ad.x); v.y = lrelu(av.y + ad.y);
        v.z = lrelu(av.z + ad.z); v.w = lrelu(av.w + ad.w);
        float xx = x[c];
        if (i < NC) { ev[i] = v; xv[i] = xx; }
        mx.x = fmaxf(mx.x, v.x); mx.y = fmaxf(mx.y, v.y);
        mx.z = fmaxf(mx.z, v.z); mx.w = fmaxf(mx.w, v.w);
    }
    #pragma unroll
    for (int o = 16; o; o >>= 1) {
        mx.x = fmaxf(mx.x, __shfl_xor_sync(0xffffffffu, mx.x, o));
        mx.y = fmaxf(mx.y, __shfl_xor_sync(0xffffffffu, mx.y, o));
        mx.z = fmaxf(mx.z, __shfl_xor_sync(0xffffffffu, mx.z, o));
        mx.w = fmaxf(mx.w, __shfl_xor_sync(0xffffffffu, mx.w, o));
    }
    float4 sm = make_float4(0, 0, 0, 0);
    i = 0;
    for (int p = b + lane; p < e2; p += 32, i++) {
        float4 v;
        if (i < NC) v = ev[i];
        else {
            int c = g_col[p];
            float4 av = ((const float4*)g_as)[c];
            v.x = lrelu(av.x + ad.x); v.y = lrelu(av.y + ad.y);
            v.z = lrelu(av.z + ad.z); v.w = lrelu(av.w + ad.w);
        }
        v.x = expf(v.x - mx.x); v.y = expf(v.y - mx.y);
        v.z = expf(v.z - mx.z); v.w = expf(v.w - mx.w);
        if (i < NC) ev[i] = v;
        sm.x += v.x; sm.y += v.y; sm.z += v.z; sm.w += v.w;
    }
    #pragma unroll
    for (int o = 16; o; o >>= 1) {
        sm.x += __shfl_xor_sync(0xffffffffu, sm.x, o);
        sm.y += __shfl_xor_sync(0xffffffffu, sm.y, o);
        sm.z += __shfl_xor_sync(0xffffffffu, sm.z, o);
        sm.w += __shfl_xor_sync(0xffffffffu, sm.w, o);
    }
    float4 inv;
    inv.x = 1.f / (sm.x + 1e-16f); inv.y = 1.f / (sm.y + 1e-16f);
    inv.z = 1.f / (sm.z + 1e-16f); inv.w = 1.f / (sm.w + 1e-16f);
    float4 acc = make_float4(0, 0, 0, 0);
    i = 0;
    for (int p = b + lane; p < e2; p += 32, i++) {
        float4 al; float xx;
        if (i < NC) { al = ev[i]; xx = xv[i]; }
        else {
            int c = g_col[p];
            float4 av = ((const float4*)g_as)[c];
            al.x = expf(lrelu(av.x + ad.x) - mx.x);
            al.y = expf(lrelu(av.y + ad.y) - mx.y);
            al.z = expf(lrelu(av.z + ad.z) - mx.z);
            al.w = expf(lrelu(av.w + ad.w) - mx.w);
            xx = x[c];
        }
        acc.x += al.x * inv.x * xx; acc.y += al.y * inv.y * xx;
        acc.z += al.z * inv.z * xx; acc.w += al.w * inv.w * xx;
    }
    #pragma unroll
    for (int o = 16; o; o >>= 1) {
        acc.x += __shfl_xor_sync(0xffffffffu, acc.x, o);
        acc.y += __shfl_xor_sync(0xffffffffu, acc.y, o);
        acc.z += __shfl_xor_sync(0xffffffffu, acc.z, o);
        acc.w += __shfl_xor_sync(0xffffffffu, acc.w, o);
    }
    int head = lane >> 3;
    float hv = (head == 0) ? acc.x : (head == 1) ? acc.y : (head == 2) ? acc.z : acc.w;
    int c0 = lane * 8;
    const float4* wp = (const float4*)&W1[c0];
    const float4* bp = (const float4*)&b1[c0];
    float4 w0 = wp[0], w1 = wp[1], bb0 = bp[0], bb1 = bp[1];
    float4 o0, o1;
    o0.x = geluf(hv * w0.x + bb0.x); o0.y = geluf(hv * w0.y + bb0.y);
    o0.z = geluf(hv * w0.z + bb0.z); o0.w = geluf(hv * w0.w + bb0.w);
    o1.x = geluf(hv * w1.x + bb1.x); o1.y = geluf(hv * w1.y + bb1.y);
    o1.z = geluf(hv * w1.z + bb1.z); o1.w = geluf(hv * w1.w + bb1.w);
    float4* xp = (float4*)&g_X[d * 256 + c0];
    xp[0] = o0; xp[1] = o1;
    uint4 xb;
    xb.x = packbf2(o0.x, o0.y); xb.y = packbf2(o0.z, o0.w);
    xb.z = packbf2(o1.x, o1.y); xb.w = packbf2(o1.z, o1.w);
    ((uint4*)&g_Xb[d * 128])[lane] = xb;
}

// ---- bf16 TC GEMM (m16n8k16) with ldmatrix fragments ------------------------
// dyn smem (words): A [2][128][20] + B [2][64][20] = 7680 words = 30720 bytes
#define ASTW  2560
#define BOFFW 5120
#define BSTW  1280
__global__ void __launch_bounds__(256, 4) k_gemm(int l,
                                                 const float* __restrict__ att_s,
                                                 const float* __restrict__ att_d, int M) {
    extern __shared__ unsigned smw[];
    __shared__ float s_pas[128], s_pad[128];
    uint32_t sbase;
    asm("{ .reg .u64 t; cvta.to.shared.u64 t, %1; cvt.u32.u64 %0, t; }"
        : "=r"(sbase) : "l"(smw));
    const unsigned* Wb = g_W2b + l * 32768;
    int tid = threadIdx.x;
    int lane = tid & 31;
    int wid = tid >> 5;
    int wm = (wid & 3) * 32;
    int wng = wid >> 2;
    int wn = wng * 32;
    int m0 = blockIdx.x * 128;
    int n0 = blockIdx.y * 64;

    float acc[2][4][4];
    #pragma unroll
    for (int mi = 0; mi < 2; mi++)
        #pragma unroll
        for (int ni = 0; ni < 4; ni++)
            #pragma unroll
            for (int q = 0; q < 4; q++) acc[mi][ni][q] = 0.f;

    auto load_stage = [&](int s, int k0w) {
        #pragma unroll
        for (int i = 0; i < 2; i++) {
            int g = tid + i * 256;
            int m = g >> 2, kq = (g & 3) * 4;
            int gm = m0 + m;
            const unsigned* src = &g_Xb[(long long)((gm < M) ? gm : 0) * 128 + k0w + kq];
            uint32_t dst = sbase + (s * ASTW + m * 20 + kq) * 4;
            int sz = (gm < M) ? 16 : 0;
            asm volatile("cp.async.cg.shared.global [%0],[%1],16,%2;"
                         :: "r"(dst), "l"(src), "r"(sz));
        }
        {
            int nn = tid >> 2, kq = (tid & 3) * 4;
            const unsigned* src = &Wb[(n0 + nn) * 128 + k0w + kq];
            uint32_t dst = sbase + (BOFFW + s * BSTW + nn * 20 + kq) * 4;
            asm volatile("cp.async.cg.shared.global [%0],[%1],16,%2;"
                         :: "r"(dst), "l"(src), "r"(16));
        }
        asm volatile("cp.async.commit_group;");
    };

    load_stage(0, 0);
    int c4 = lane & 3, r8 = lane >> 2;
    int grp = lane >> 3, l8 = lane & 7;
    int aRow = wm + (grp & 1) * 8 + l8;
    int aWrd = (grp >> 1) * 4;
    int bRow = wn + (grp >> 1) * 8 + l8;
    int bWrd = (grp & 1) * 4;

    for (int it = 0; it < 8; it++) {
        int s = it & 1;
        asm volatile("cp.async.wait_group 0;");
        __syncthreads();
        if (it < 7) load_stage((it + 1) & 1, (it + 1) * 16);
        #pragma unroll
        for (int ks = 0; ks < 2; ks++) {
            int kw = ks * 8;
            unsigned a[2][4], bf[4][2];
            #pragma unroll
            for (int mi = 0; mi < 2; mi++) {
                uint32_t addr = sbase + (s * ASTW + (aRow + mi * 16) * 20 + kw + aWrd) * 4;
                ldmx4(a[mi], addr);
            }
            #pragma unroll
            for (int nip = 0; nip < 2; nip++) {
                unsigned q[4];
                uint32_t addr = sbase + (BOFFW + s * BSTW + (bRow + nip * 16) * 20 + kw + bWrd) * 4;
                ldmx4(q, addr);
                bf[2 * nip][0] = q[0]; bf[2 * nip][1] = q[1];
                bf[2 * nip + 1][0] = q[2]; bf[2 * nip + 1][1] = q[3];
            }
            #pragma unroll
            for (int mi = 0; mi < 2; mi++)
                #pragma unroll
                for (int ni = 0; ni < 4; ni++)
                    mma_bf16(acc[mi][ni], a[mi], bf[ni]);
        }
    }
    float pas[4] = {0, 0, 0, 0}, pad_[4] = {0, 0, 0, 0};
    #pragma unroll
    for (int mi = 0; mi < 2; mi++) {
        int m = m0 + wm + mi * 16 + r8;
        #pragma unroll
        for (int ni = 0; ni < 4; ni++) {
            int nn = n0 + wn + ni * 8 + 2 * c4;
            float s0 = __ldg(&att_s[nn]), s1 = __ldg(&att_s[nn + 1]);
            float d0 = __ldg(&att_d[nn]), d1 = __ldg(&att_d[nn + 1]);
            pas[2 * mi]     += acc[mi][ni][0] * s0 + acc[mi][ni][1] * s1;
            pas[2 * mi + 1] += acc[mi][ni][2] * s0 + acc[mi][ni][3] * s1;
            pad_[2 * mi]     += acc[mi][ni][0] * d0 + acc[mi][ni][1] * d1;
            pad_[2 * mi + 1] += acc[mi][ni][2] * d0 + acc[mi][ni][3] * d1;
            if (m < M)
                g_Hb[m * 128 + (nn >> 1)] = packbf2(acc[mi][ni][0], acc[mi][ni][1]);
            if (m + 8 < M)
                g_Hb[(m + 8) * 128 + (nn >> 1)] = packbf2(acc[mi][ni][2], acc[mi][ni][3]);
        }
    }
    #pragma unroll
    for (int off = 1; off < 4; off <<= 1) {
        #pragma unroll
        for (int r = 0; r < 4; r++) {
            pas[r]  += __shfl_xor_sync(0xffffffffu, pas[r], off);
            pad_[r] += __shfl_xor_sync(0xffffffffu, pad_[r], off);
        }
    }
    if (c4 == 0 && wng == 1) {
        #pragma unroll
        for (int r = 0; r < 4; r++) {
            int row = wm + r8 + (r & 1) * 8 + (r >> 1) * 16;
            s_pas[row] = pas[r]; s_pad[row] = pad_[r];
        }
    }
    __syncthreads();
    if (c4 == 0 && wng == 0) {
        #pragma unroll
        for (int r = 0; r < 4; r++) {
            int row = wm + r8 + (r & 1) * 8 + (r >> 1) * 16;
            int m = m0 + row;
            if (m < M) {
                g_as[m * 4 + blockIdx.y] = pas[r] + s_pas[row];
                g_ad[m * 4 + blockIdx.y] = pad_[r] + s_pad[row];
            }
        }
    }
}

// ------- fused edge softmax + aggregation (layers 2-4), warp per dst ---------
// smem-staged alpha/rowbase broadcast + packed f32x2 FMA in the gather loop
__global__ void __launch_bounds__(256) k_fatt(const float* __restrict__ bias, int n,
                                              float* __restrict__ alpha_out, int last) {
    __shared__ float2 stage[8][32];
    int wid = threadIdx.x >> 5, lane = threadIdx.x & 31;
    int d = blockIdx.x * 8 + wid;
    if (d >= n) return;
    int b = g_row[d], e = g_row[d + 1];
    float4 dv = ((const float4*)g_ad)[d];
    float ad = (dv.x + dv.y) + (dv.z + dv.w);
    const int NC = 8;
    float ev[NC]; int col[NC];
    float mx = -1e30f;
    int i = 0;
    for (int p = b + lane; p < e; p += 32, i++) {
        int c = g_col[p];
        float4 sv = ((const float4*)g_as)[c];
        float v = lrelu((sv.x + sv.y) + (sv.z + sv.w) + ad);
        if (i < NC) { ev[i] = v; col[i] = c; }
        mx = fmaxf(mx, v);
    }
    #pragma unroll
    for (int o = 16; o; o >>= 1) mx = fmaxf(mx, __shfl_xor_sync(0xffffffffu, mx, o));
    float sm = 0.f;
    i = 0;
    for (int p = b + lane; p < e; p += 32, i++) {
        float v;
        if (i < NC) v = ev[i];
        else {
            float4 sv = ((const float4*)g_as)[g_col[p]];
            v = lrelu((sv.x + sv.y) + (sv.z + sv.w) + ad);
        }
        v = expf(v - mx);
        if (i < NC) ev[i] = v;
        sm += v;
    }
    #pragma unroll
    for (int o = 16; o; o >>= 1) sm += __shfl_xor_sync(0xffffffffu, sm, o);
    float inv = 1.f / (sm + 1e-16f);

    unsigned long long acc2[4] = {0ull, 0ull, 0ull, 0ull};
    int lane4 = lane * 4;          // uint offset within row (uint4 slot)
    for (int base = b; base < e; base += 32) {
        int p = base + lane;
        int idx = (base - b) >> 5;
        float aa = 0.f; int cc = 0;
        if (p < e) {
            if (idx < NC) { aa = ev[idx] * inv; cc = col[idx]; }
            else {
                cc = g_col[p];
                float4 sv = ((const float4*)g_as)[cc];
                aa = expf(lrelu((sv.x + sv.y) + (sv.z + sv.w) + ad) - mx) * inv;
            }
            if (alpha_out) alpha_out[g_eid[p]] = aa;
        }
        stage[wid][lane] = make_float2(aa, __int_as_float(cc * 128));
        __syncwarp();
        int lim = min(32, e - base);
        #pragma unroll 4
        for (int t = 0; t < lim; t++) {
            float2 sc = stage[wid][t];
            unsigned long long ap;
            asm("mov.b64 %0, {%1,%2};" : "=l"(ap) : "f"(sc.x), "f"(sc.x));
            const uint4* hp = (const uint4*)(g_Hb + __float_as_int(sc.y) + lane4);
            uint4 v = *hp;
            ffma2(acc2[0], v.x << 16, v.x & 0xFFFF0000u, ap);
            ffma2(acc2[1], v.y << 16, v.y & 0xFFFF0000u, ap);
            ffma2(acc2[2], v.z << 16, v.z & 0xFFFF0000u, ap);
            ffma2(acc2[3], v.w << 16, v.w & 0xFFFF0000u, ap);
        }
        __syncwarp();
    }
    float acc[8];
    #pragma unroll
    for (int j = 0; j < 4; j++)
        asm("mov.b64 {%0,%1}, %2;" : "=f"(acc[2 * j]), "=f"(acc[2 * j + 1]) : "l"(acc2[j]));
    float4 o0, o1;
    const float4* bv = (const float4*)&bias[lane * 8];
    float4 b0 = bv[0], b1 = bv[1];
    o0.x = geluf(acc[0] + b0.x); o0.y = geluf(acc[1] + b0.y);
    o0.z = geluf(acc[2] + b0.z); o0.w = geluf(acc[3] + b0.w);
    o1.x = geluf(acc[4] + b1.x); o1.y = geluf(acc[5] + b1.y);
    o1.z = geluf(acc[6] + b1.z); o1.w = geluf(acc[7] + b1.w);
    float4* xp = (float4*)&g_X[d * 256 + lane * 8];
    xp[0] = o0; xp[1] = o1;
    if (!last) {
        uint4 xb;
        xb.x = packbf2(o0.x, o0.y); xb.y = packbf2(o0.z, o0.w);
        xb.z = packbf2(o1.x, o1.y); xb.w = packbf2(o1.z, o1.w);
        ((uint4*)&g_Xb[d * 128])[lane] = xb;
    }
}

// ---- pool (blocks 0-15) + MLP head (block 16, spin-wait) --------------------
__global__ void __launch_bounds__(512) k_poolmlp(const float* __restrict__ Wl1, const float* __restrict__ bl1,
                                                 const float* __restrict__ Wl2, const float* __restrict__ bl2,
                                                 const float* __restrict__ Wl3, const float* __restrict__ bl3,
                                                 float* __restrict__ out) {
    int t = threadIdx.x;
    if (blockIdx.x < NGRAPH) {
        __shared__ float sbuf[8][256];
        int g = blockIdx.x;
        int s = t >> 6, c4 = t & 63;
        int b = g_goff[g], e = g_goff[g + 1];
        float4 acc = make_float4(0, 0, 0, 0);
        for (int i = b + s; i < e; i += 8) {
            float4 v = *(const float4*)&g_X[i * 256 + c4 * 4];
            acc.x += v.x; acc.y += v.y; acc.z += v.z; acc.w += v.w;
        }
        *(float4*)&sbuf[s][c4 * 4] = acc;
        __syncthreads();
        if (s == 0) {
            #pragma unroll
            for (int k = 0; k < 4; k++) {
                int c = c4 * 4 + k;
                float v = 0.f;
                #pragma unroll
                for (int r = 0; r < 8; r++) v += sbuf[r][c];
                g_gsum[g * 256 + c] = v;
            }
        }
        __threadfence();
        __syncthreads();
        if (t == 0) atomicAdd(&g_done, 1);
        return;
    }
    if (t == 0) {
        while (atomicAdd(&g_done, 0) < NGRAPH) __nanosleep(200);
    }
    __syncthreads();
    __threadfence();
    __shared__ float G[16 * 256];
    __shared__ float G1[16 * 128];
    __shared__ float G2[16 * 64];
    for (int i = t; i < 4096; i += 512) {
        int g = i >> 8;
        int cnt = g_goff[g + 1] - g_goff[g];
        G[i] = g_gsum[i] / (float)(cnt > 0 ? cnt : 1);
    }
    __syncthreads();
    for (int i = t; i < 2048; i += 512) {
        int gi = i >> 7, j = i & 127;
        float a = bl1[j];
        for (int k = 0; k < 256; k++) a += G[gi * 256 + k] * Wl1[k * 128 + j];
        G1[i] = geluf(a);
    }
    __syncthreads();
    for (int i = t; i < 1024; i += 512) {
        int gi = i >> 6, j = i & 63;
        float a = bl2[j];
        for (int k = 0; k < 128; k++) a += G1[gi * 128 + k] * Wl2[k * 64 + j];
        G2[i] = geluf(a);
    }
    __syncthreads();
    if (t < 16) {
        float a = bl3[0];
        for (int k = 0; k < 64; k++) a += G2[t * 64 + k] * Wl3[k];
        out[t] = 1.f / (1.f + expf(-a));
    }
}

// ---------------- host launcher ------------------------------------------------
extern "C" void kernel_launch(void* const* d_in, const int* in_sizes, int n_in,
                              void* d_out, int out_size) {
    const float* x     = (const float*)d_in[0];
    const void*  ei    = d_in[1];
    const void*  batch = d_in[2];
    const float* W1  = (const float*)d_in[3];
    const float* as1 = (const float*)d_in[4];
    const float* ad1 = (const float*)d_in[5];
    const float* b1  = (const float*)d_in[6];
    const float* W2  = (const float*)d_in[7];
    const float* as2 = (const float*)d_in[8];
    const float* ad2 = (const float*)d_in[9];
    const float* b2  = (const float*)d_in[10];
    const float* Wl1 = (const float*)d_in[11];
    const float* bl1 = (const float*)d_in[12];
    const float* Wl2 = (const float*)d_in[13];
    const float* bl2 = (const float*)d_in[14];
    const float* Wl3 = (const float*)d_in[15];
    const float* bl3 = (const float*)d_in[16];

    int Nn = in_sizes[0];
    int E = in_sizes[1] / 2;
    int Etot = E + Nn;
    float* out = (float*)d_out;
    bool full = (out_size >= 16 + 3 * Etot);
    float* attn_out  = full ? (out + 16) : nullptr;
    float* alpha_out = full ? (out + 16 + 2 * Etot) : nullptr;

    int NBfill = (Etot + 255) / 256;
    int NBf1   = (Nn + 7) / 8;
    int NBgrid = (NBf1 > NBfill) ? NBf1 : NBfill;

    cudaFuncSetAttribute(k_gemm, cudaFuncAttributeMaxDynamicSharedMemorySize, 30720);

    // 1: detect + prep1 + deg count + sd1 + bounds + W2 pack + counter reset
    k_pre<<<(Etot + 255) / 256, 256>>>(ei, x, batch, W1, as1, ad1, W2, E, Etot, Nn);
    // 2: prefix scan (self-cleans g_deg)
    k_scan<<<1, 1024>>>(Nn);
    // 3: CSR fill + attn idx + fused layer 1
    k_fillf1<<<NBgrid, 256>>>(ei, E, Etot, Nn, NBfill, attn_out, x, W1, b1);
    // 4-9: layers 2-4
    for (int l = 0; l < 3; l++) {
        k_gemm<<<dim3((Nn + 127) / 128, 4), 256, 30720>>>(l, as2 + l * 256,
                                                          ad2 + l * 256, Nn);
        k_fatt<<<(Nn + 7) / 8, 256>>>(b2 + l * 256, Nn,
                                      (l == 2) ? alpha_out : nullptr, l == 2);
    }
    // 10: pool + MLP head
    k_poolmlp<<<NGRAPH + 1, 512>>>(Wl1, bl1, Wl2, bl2, Wl3, bl3, out);
}

// round 17
// speedup vs baseline: 1.1564x; 1.0156x over previous
#include <cuda_runtime.h>
#include <cuda_bf16.h>
#include <math.h>
#include <stdint.h>

#define NMAX   20000
#define ETOT_MAX 340000
#define DD     256
#define NGRAPH 16

// ---------------- scratch (static device globals; no allocation) -------------
__device__ float    g_X[NMAX * DD];             // fp32 features (pool reads this)
__device__ __align__(16) unsigned g_Xb[NMAX * 128];   // bf16x2-packed X (GEMM A input)
__device__ __align__(16) unsigned g_Hb[NMAX * 128];   // bf16x2-packed H (gather input)
__device__ __align__(16) unsigned g_W2b[3 * 32768];   // bf16 W2, n-major [l][n][k2]
__device__ float    g_as[NMAX * 4];
__device__ float    g_ad[NMAX * 4];
__device__ int      g_deg[NMAX];                // zero-init; re-zeroed by k_scan
__device__ int      g_row[NMAX + 1];
__device__ int      g_cur[NMAX];
__device__ int      g_col[ETOT_MAX];
__device__ int      g_eid[ETOT_MAX];
__device__ float    g_gsum[NGRAPH * DD];
__device__ int      g_goff[NGRAPH + 1];
__device__ int      g_is64;
__device__ int      g_done;
__device__ int      g_done2;
__device__ int      g_tkt;

// ---------------- helpers ----------------------------------------------------
__device__ __forceinline__ float geluf(float x) {
    float u = 0.7978845608028654f * (x + 0.044715f * x * x * x);
    float t;
    asm("tanh.approx.f32 %0, %1;" : "=f"(t) : "f"(u));
    return 0.5f * x * (1.0f + t);
}
__device__ __forceinline__ float lrelu(float x) { return x > 0.f ? x : 0.2f * x; }

__device__ __forceinline__ long long load_idx(const void* p, long long i) {
    if (g_is64) return ((const long long*)p)[i];
    return (long long)((const int*)p)[i];
}
__device__ __forceinline__ long long load_idx2(const void* p, long long i, int is64) {
    if (is64) return ((const long long*)p)[i];
    return (long long)((const int*)p)[i];
}
__device__ __forceinline__ void mma_bf16(float* c, const unsigned* a, const unsigned* b) {
    asm volatile(
        "mma.sync.aligned.m16n8k16.row.col.f32.bf16.bf16.f32 "
        "{%0,%1,%2,%3},{%4,%5,%6,%7},{%8,%9},{%0,%1,%2,%3};"
        : "+f"(c[0]), "+f"(c[1]), "+f"(c[2]), "+f"(c[3])
        : "r"(a[0]), "r"(a[1]), "r"(a[2]), "r"(a[3]), "r"(b[0]), "r"(b[1]));
}
__device__ __forceinline__ void ldmx4(unsigned* r, uint32_t addr) {
    asm volatile("ldmatrix.sync.aligned.m8n8.x4.shared.b16 {%0,%1,%2,%3}, [%4];"
                 : "=r"(r[0]), "=r"(r[1]), "=r"(r[2]), "=r"(r[3]) : "r"(addr));
}
__device__ __forceinline__ unsigned packbf2(float lo, float hi) {
    __nv_bfloat162 t = __floats2bfloat162_rn(lo, hi);
    return *(unsigned*)&t;
}
// f32x2 packed fma: acc += d * ap (element-wise on register pairs)
__device__ __forceinline__ void ffma2(unsigned long long& acc, unsigned lo, unsigned hi,
                                      unsigned long long ap) {
    unsigned long long d;
    asm("mov.b64 %0, {%1,%2};" : "=l"(d) : "r"(lo), "r"(hi));
    asm("fma.rn.f32x2 %0, %1, %2, %0;" : "+l"(acc) : "l"(d), "l"(ap));
}

// ---- kernel 1: detect + prep1 + deg count + sd1 + bounds + W2->bf16 ---------
__global__ void __launch_bounds__(256) k_pre(const void* __restrict__ ei,
                                             const float* __restrict__ x,
                                             const void* __restrict__ batch,
                                             const float* __restrict__ W1,
                                             const float* __restrict__ as1,
                                             const float* __restrict__ ad1,
                                             const float* __restrict__ W2,
                                             int E, int Etot, int n) {
    __shared__ int nz;
    __shared__ float ss[256], sd[256];
    __shared__ float scs[4], scd[4];
    int tid = threadIdx.x;
    if (tid == 0) nz = 0;
    __syncthreads();
    const int* w32 = (const int*)ei;
    int lim = min(E, 4096);
    for (int j = tid; j < lim; j += 256)
        if (w32[2 * j + 1] != 0) nz = 1;
    float w = W1[tid];
    ss[tid] = w * as1[tid];
    sd[tid] = w * ad1[tid];
    __syncthreads();
    int is64 = (nz == 0) ? 1 : 0;
    for (int off = 32; off; off >>= 1) {
        if ((tid & 63) < off) { ss[tid] += ss[tid + off]; sd[tid] += sd[tid + off]; }
        __syncthreads();
    }
    if ((tid & 63) == 0) { scs[tid >> 6] = ss[tid]; scd[tid >> 6] = sd[tid]; }
    __syncthreads();

    int e = blockIdx.x * 256 + tid;
    if (e == 0) { g_done = 0; g_done2 = 0; g_tkt = 0; g_is64 = is64; }
    // W2 -> bf16 n-major: g_W2b[l*32768 + n*128 + k2]
    const int nI = 3 * 128 * 64;
    int gstride = gridDim.x * 256;
    for (int idx = e; idx < nI; idx += gstride) {
        int l = idx / 8192, r = idx - l * 8192;
        int k2 = r >> 6, n4 = (r & 63) * 4;
        const float* base = W2 + l * 65536 + (2 * k2) * 256 + n4;
        float4 lo = *(const float4*)base;
        float4 hi = *(const float4*)(base + 256);
        unsigned* dst = g_W2b + l * 32768 + n4 * 128 + k2;
        dst[0]   = packbf2(lo.x, hi.x);
        dst[128] = packbf2(lo.y, hi.y);
        dst[256] = packbf2(lo.z, hi.z);
        dst[384] = packbf2(lo.w, hi.w);
    }
    if (e < Etot) {
        int dst = (e < E) ? (int)load_idx2(ei, (long long)E + e, is64) : (e - E);
        if (dst >= 0 && dst < n) atomicAdd(&g_deg[dst], 1);
    }
    if (e < n) {
        float xv = x[e];
        #pragma unroll
        for (int h = 0; h < 4; h++) {
            g_as[e * 4 + h] = xv * scs[h];
            g_ad[e * 4 + h] = xv * scd[h];
        }
        int b = (int)load_idx2(batch, e, is64);
        int prev = (e == 0) ? -1 : (int)load_idx2(batch, e - 1, is64);
        for (int g = prev + 1; g <= b && g <= NGRAPH; g++)
            if (g >= 0) g_goff[g] = e;
        if (e == n - 1)
            for (int g = b + 1; g <= NGRAPH; g++) g_goff[g] = n;
    }
}

// ---- kernel 2: coalesced two-phase scan (self-cleans g_deg) ------------------
__global__ void __launch_bounds__(1024) k_scan(int n) {
    __shared__ int sbuf[10240];
    __shared__ int wsum[32];
    int t = threadIdx.x, lane = t & 31, w = t >> 5;
    int carry = 0;
    #pragma unroll
    for (int ph = 0; ph < 2; ph++) {
        int base = ph * 10240;
        #pragma unroll
        for (int j = 0; j < 10; j++) {
            int idx = base + j * 1024 + t;
            int v = (idx < n) ? g_deg[idx] : 0;
            sbuf[j * 1024 + t] = v;
            if (idx < n) g_deg[idx] = 0;
        }
        __syncthreads();
        int vals[10], sum = 0;
        #pragma unroll
        for (int i = 0; i < 10; i++) { vals[i] = sbuf[t * 10 + i]; sum += vals[i]; }
        int s = sum;
        #pragma unroll
        for (int off = 1; off < 32; off <<= 1) {
            int v = __shfl_up_sync(0xffffffffu, s, off);
            if (lane >= off) s += v;
        }
        if (lane == 31) wsum[w] = s;
        __syncthreads();
        if (w == 0) {
            int x = wsum[lane];
            #pragma unroll
            for (int off = 1; off < 32; off <<= 1) {
                int v = __shfl_up_sync(0xffffffffu, x, off);
                if (lane >= off) x += v;
            }
            wsum[lane] = x;
        }
        __syncthreads();
        int excl = s - sum + (w > 0 ? wsum[w - 1] : 0) + carry;
        int total = wsum[31];
        __syncthreads();
        int run = excl;
        #pragma unroll
        for (int i = 0; i < 10; i++) { sbuf[t * 10 + i] = run; run += vals[i]; }
        __syncthreads();
        #pragma unroll
        for (int j = 0; j < 10; j++) {
            int idx = base + j * 1024 + t;
            if (idx < n) { int v = sbuf[j * 1024 + t]; g_row[idx] = v; g_cur[idx] = v; }
        }
        carry += total;
        __syncthreads();
    }
    if (t == 0) g_row[n] = carry;
}

// ---- kernel 3: CSR fill (ticket queue) + attn idx + fused layer 1 -----------
__global__ void __launch_bounds__(256) k_fillf1(const void* __restrict__ ei,
                                                int E, int Etot, int n, int NBfill,
                                                float* __restrict__ attn_dst,
                                                const float* __restrict__ x,
                                                const float* __restrict__ W1,
                                                const float* __restrict__ b1) {
    int tid = threadIdx.x;
    __shared__ int schunk;
    int mychunks = 0;
    for (;;) {
        if (tid == 0) schunk = atomicAdd(&g_tkt, 1);
        __syncthreads();
        int chunk = schunk;
        __syncthreads();
        if (chunk >= NBfill) break;
        mychunks++;
        int e = chunk * 256 + tid;
        if (e < Etot) {
            int src, dst;
            if (e < E) {
                src = (int)load_idx(ei, e);
                dst = (int)load_idx(ei, (long long)E + e);
            } else { src = e - E; dst = e - E; }
            if (attn_dst) {
                attn_dst[e] = (float)src;
                attn_dst[Etot + e] = (float)dst;
            }
            if (dst >= 0 && dst < n && src >= 0 && src < n) {
                int pos = atomicAdd(&g_cur[dst], 1);
                g_col[pos] = src;
                g_eid[pos] = e;
            }
        }
    }
    __threadfence();
    __syncthreads();
    if (tid == 0) {
        if (mychunks) atomicAdd(&g_done2, mychunks);
        while (atomicAdd(&g_done2, 0) < NBfill) __nanosleep(100);
    }
    __syncthreads();
    __threadfence();
    // ---- phase 2: fused layer 1 ----
    int wid = tid >> 5, lane = tid & 31;
    int d = blockIdx.x * 8 + wid;
    if (d >= n) return;
    int b = g_row[d], e2 = g_row[d + 1];
    float4 ad = ((const float4*)g_ad)[d];
    const int NC = 4;
    float4 ev[NC]; float xv[NC];
    float4 mx = make_float4(-1e30f, -1e30f, -1e30f, -1e30f);
    int i = 0;
    for (int p = b + lane; p < e2; p += 32, i++) {
        int c = g_col[p];
        float4 av = ((const float4*)g_as)[c];
        float4 v;
        v.x = lrelu(av.x + ad.x); v.y = lrelu(av.y + ad.y);
        v.z = lrelu(av.z + ad.z); v.w = lrelu(av.w + ad.w);
        float xx = x[c];
        if (i < NC) { ev[i] = v; xv[i] = xx; }
        mx.x = fmaxf(mx.x, v.x); mx.y = fmaxf(mx.y, v.y);
        mx.z = fmaxf(mx.z, v.z); mx.w = fmaxf(mx.w, v.w);
    }
    #pragma unroll
    for (int o = 16; o; o >>= 1) {
        mx.x = fmaxf(mx.x, __shfl_xor_sync(0xffffffffu, mx.x, o));
        mx.y = fmaxf(mx.y, __shfl_xor_sync(0xffffffffu, mx.y, o));
        mx.z = fmaxf(mx.z, __shfl_xor_sync(0xffffffffu, mx.z, o));
        mx.w = fmaxf(mx.w, __shfl_xor_sync(0xffffffffu, mx.w, o));
    }
    float4 sm = make_float4(0, 0, 0, 0);
    i = 0;
    for (int p = b + lane; p < e2; p += 32, i++) {
        float4 v;
        if (i < NC) v = ev[i];
        else {
            int c = g_col[p];
            float4 av = ((const float4*)g_as)[c];
            v.x = lrelu(av.x + ad.x); v.y = lrelu(av.y + ad.y);
            v.z = lrelu(av.z + ad.z); v.w = lrelu(av.w + ad.w);
        }
        v.x = __expf(v.x - mx.x); v.y = __expf(v.y - mx.y);
        v.z = __expf(v.z - mx.z); v.w = __expf(v.w - mx.w);
        if (i < NC) ev[i] = v;
        sm.x += v.x; sm.y += v.y; sm.z += v.z; sm.w += v.w;
    }
    #pragma unroll
    for (int o = 16; o; o >>= 1) {
        sm.x += __shfl_xor_sync(0xffffffffu, sm.x, o);
        sm.y += __shfl_xor_sync(0xffffffffu, sm.y, o);
        sm.z += __shfl_xor_sync(0xffffffffu, sm.z, o);
        sm.w += __shfl_xor_sync(0xffffffffu, sm.w, o);
    }
    float4 inv;
    inv.x = 1.f / (sm.x + 1e-16f); inv.y = 1.f / (sm.y + 1e-16f);
    inv.z = 1.f / (sm.z + 1e-16f); inv.w = 1.f / (sm.w + 1e-16f);
    float4 acc = make_float4(0, 0, 0, 0);
    i = 0;
    for (int p = b + lane; p < e2; p += 32, i++) {
        float4 al; float xx;
        if (i < NC) { al = ev[i]; xx = xv[i]; }
        else {
            int c = g_col[p];
            float4 av = ((const float4*)g_as)[c];
            al.x = __expf(lrelu(av.x + ad.x) - mx.x);
            al.y = __expf(lrelu(av.y + ad.y) - mx.y);
            al.z = __expf(lrelu(av.z + ad.z) - mx.z);
            al.w = __expf(lrelu(av.w + ad.w) - mx.w);
            xx = x[c];
        }
        acc.x += al.x * inv.x * xx; acc.y += al.y * inv.y * xx;
        acc.z += al.z * inv.z * xx; acc.w += al.w * inv.w * xx;
    }
    #pragma unroll
    for (int o = 16; o; o >>= 1) {
        acc.x += __shfl_xor_sync(0xffffffffu, acc.x, o);
        acc.y += __shfl_xor_sync(0xffffffffu, acc.y, o);
        acc.z += __shfl_xor_sync(0xffffffffu, acc.z, o);
        acc.w += __shfl_xor_sync(0xffffffffu, acc.w, o);
    }
    int head = lane >> 3;
    float hv = (head == 0) ? acc.x : (head == 1) ? acc.y : (head == 2) ? acc.z : acc.w;
    int c0 = lane * 8;
    const float4* wp = (const float4*)&W1[c0];
    const float4* bp = (const float4*)&b1[c0];
    float4 w0 = wp[0], w1 = wp[1], bb0 = bp[0], bb1 = bp[1];
    float4 o0, o1;
    o0.x = geluf(hv * w0.x + bb0.x); o0.y = geluf(hv * w0.y + bb0.y);
    o0.z = geluf(hv * w0.z + bb0.z); o0.w = geluf(hv * w0.w + bb0.w);
    o1.x = geluf(hv * w1.x + bb1.x); o1.y = geluf(hv * w1.y + bb1.y);
    o1.z = geluf(hv * w1.z + bb1.z); o1.w = geluf(hv * w1.w + bb1.w);
    float4* xp = (float4*)&g_X[d * 256 + c0];
    xp[0] = o0; xp[1] = o1;
    uint4 xb;
    xb.x = packbf2(o0.x, o0.y); xb.y = packbf2(o0.z, o0.w);
    xb.z = packbf2(o1.x, o1.y); xb.w = packbf2(o1.z, o1.w);
    ((uint4*)&g_Xb[d * 128])[lane] = xb;
}

// ---- bf16 TC GEMM (m16n8k16): 3-stage cp.async + ldmatrix -------------------
// dyn smem (words): A [3][128][20] + B [3][64][20] = 11520 words = 46080 bytes
#define ASTW  2560
#define BOFFW 7680
#define BSTW  1280
__global__ void __launch_bounds__(256, 4) k_gemm(int l,
                                                 const float* __restrict__ att_s,
                                                 const float* __restrict__ att_d, int M) {
    extern __shared__ unsigned smw[];
    __shared__ float s_pas[128], s_pad[128];
    uint32_t sbase;
    asm("{ .reg .u64 t; cvta.to.shared.u64 t, %1; cvt.u32.u64 %0, t; }"
        : "=r"(sbase) : "l"(smw));
    const unsigned* Wb = g_W2b + l * 32768;
    int tid = threadIdx.x;
    int lane = tid & 31;
    int wid = tid >> 5;
    int wm = (wid & 3) * 32;
    int wng = wid >> 2;
    int wn = wng * 32;
    int m0 = blockIdx.x * 128;
    int n0 = blockIdx.y * 64;

    float acc[2][4][4];
    #pragma unroll
    for (int mi = 0; mi < 2; mi++)
        #pragma unroll
        for (int ni = 0; ni < 4; ni++)
            #pragma unroll
            for (int q = 0; q < 4; q++) acc[mi][ni][q] = 0.f;

    auto load_stage = [&](int s, int k0w) {
        #pragma unroll
        for (int i = 0; i < 2; i++) {
            int g = tid + i * 256;
            int m = g >> 2, kq = (g & 3) * 4;
            int gm = m0 + m;
            const unsigned* src = &g_Xb[(long long)((gm < M) ? gm : 0) * 128 + k0w + kq];
            uint32_t dst = sbase + (s * ASTW + m * 20 + kq) * 4;
            int sz = (gm < M) ? 16 : 0;
            asm volatile("cp.async.cg.shared.global [%0],[%1],16,%2;"
                         :: "r"(dst), "l"(src), "r"(sz));
        }
        {
            int nn = tid >> 2, kq = (tid & 3) * 4;
            const unsigned* src = &Wb[(n0 + nn) * 128 + k0w + kq];
            uint32_t dst = sbase + (BOFFW + s * BSTW + nn * 20 + kq) * 4;
            asm volatile("cp.async.cg.shared.global [%0],[%1],16,%2;"
                         :: "r"(dst), "l"(src), "r"(16));
        }
        asm volatile("cp.async.commit_group;");
    };

    load_stage(0, 0);
    load_stage(1, 16);
    int c4 = lane & 3, r8 = lane >> 2;
    int grp = lane >> 3, l8 = lane & 7;
    int aRow = wm + (grp & 1) * 8 + l8;
    int aWrd = (grp >> 1) * 4;
    int bRow = wn + (grp >> 1) * 8 + l8;
    int bWrd = (grp & 1) * 4;

    for (int it = 0; it < 8; it++) {
        int s = it % 3;
        if (it < 7) asm volatile("cp.async.wait_group 1;");
        else        asm volatile("cp.async.wait_group 0;");
        __syncthreads();
        if (it < 6) load_stage((it + 2) % 3, (it + 2) * 16);
        #pragma unroll
        for (int ks = 0; ks < 2; ks++) {
            int kw = ks * 8;
            unsigned a[2][4], bf[4][2];
            #pragma unroll
            for (int mi = 0; mi < 2; mi++) {
                uint32_t addr = sbase + (s * ASTW + (aRow + mi * 16) * 20 + kw + aWrd) * 4;
                ldmx4(a[mi], addr);
            }
            #pragma unroll
            for (int nip = 0; nip < 2; nip++) {
                unsigned q[4];
                uint32_t addr = sbase + (BOFFW + s * BSTW + (bRow + nip * 16) * 20 + kw + bWrd) * 4;
                ldmx4(q, addr);
                bf[2 * nip][0] = q[0]; bf[2 * nip][1] = q[1];
                bf[2 * nip + 1][0] = q[2]; bf[2 * nip + 1][1] = q[3];
            }
            #pragma unroll
            for (int mi = 0; mi < 2; mi++)
                #pragma unroll
                for (int ni = 0; ni < 4; ni++)
                    mma_bf16(acc[mi][ni], a[mi], bf[ni]);
        }
    }
    float pas[4] = {0, 0, 0, 0}, pad_[4] = {0, 0, 0, 0};
    #pragma unroll
    for (int mi = 0; mi < 2; mi++) {
        int m = m0 + wm + mi * 16 + r8;
        #pragma unroll
        for (int ni = 0; ni < 4; ni++) {
            int nn = n0 + wn + ni * 8 + 2 * c4;
            float s0 = __ldg(&att_s[nn]), s1 = __ldg(&att_s[nn + 1]);
            float d0 = __ldg(&att_d[nn]), d1 = __ldg(&att_d[nn + 1]);
            pas[2 * mi]     += acc[mi][ni][0] * s0 + acc[mi][ni][1] * s1;
            pas[2 * mi + 1] += acc[mi][ni][2] * s0 + acc[mi][ni][3] * s1;
            pad_[2 * mi]     += acc[mi][ni][0] * d0 + acc[mi][ni][1] * d1;
            pad_[2 * mi + 1] += acc[mi][ni][2] * d0 + acc[mi][ni][3] * d1;
            if (m < M)
                g_Hb[m * 128 + (nn >> 1)] = packbf2(acc[mi][ni][0], acc[mi][ni][1]);
            if (m + 8 < M)
                g_Hb[(m + 8) * 128 + (nn >> 1)] = packbf2(acc[mi][ni][2], acc[mi][ni][3]);
        }
    }
    #pragma unroll
    for (int off = 1; off < 4; off <<= 1) {
        #pragma unroll
        for (int r = 0; r < 4; r++) {
            pas[r]  += __shfl_xor_sync(0xffffffffu, pas[r], off);
            pad_[r] += __shfl_xor_sync(0xffffffffu, pad_[r], off);
        }
    }
    if (c4 == 0 && wng == 1) {
        #pragma unroll
        for (int r = 0; r < 4; r++) {
            int row = wm + r8 + (r & 1) * 8 + (r >> 1) * 16;
            s_pas[row] = pas[r]; s_pad[row] = pad_[r];
        }
    }
    __syncthreads();
    if (c4 == 0 && wng == 0) {
        #pragma unroll
        for (int r = 0; r < 4; r++) {
            int row = wm + r8 + (r & 1) * 8 + (r >> 1) * 16;
            int m = m0 + row;
            if (m < M) {
                g_as[m * 4 + blockIdx.y] = pas[r] + s_pas[row];
                g_ad[m * 4 + blockIdx.y] = pad_[r] + s_pad[row];
            }
        }
    }
}

// ------- fused edge softmax + aggregation (layers 2-4), warp per dst ---------
__global__ void __launch_bounds__(256) k_fatt(const float* __restrict__ bias, int n,
                                              float* __restrict__ alpha_out, int last) {
    __shared__ float2 stage[8][32];
    int wid = threadIdx.x >> 5, lane = threadIdx.x & 31;
    int d = blockIdx.x * 8 + wid;
    if (d >= n) return;
    int b = g_row[d], e = g_row[d + 1];
    float4 dv = ((const float4*)g_ad)[d];
    float ad = (dv.x + dv.y) + (dv.z + dv.w);
    const int NC = 8;
    float ev[NC]; int col[NC];
    float mx = -1e30f;
    int i = 0;
    for (int p = b + lane; p < e; p += 32, i++) {
        int c = g_col[p];
        float4 sv = ((const float4*)g_as)[c];
        float v = lrelu((sv.x + sv.y) + (sv.z + sv.w) + ad);
        if (i < NC) { ev[i] = v; col[i] = c; }
        mx = fmaxf(mx, v);
    }
    #pragma unroll
    for (int o = 16; o; o >>= 1) mx = fmaxf(mx, __shfl_xor_sync(0xffffffffu, mx, o));
    float sm = 0.f;
    i = 0;
    for (int p = b + lane; p < e; p += 32, i++) {
        float v;
        if (i < NC) v = ev[i];
        else {
            float4 sv = ((const float4*)g_as)[g_col[p]];
            v = lrelu((sv.x + sv.y) + (sv.z + sv.w) + ad);
        }
        v = __expf(v - mx);
        if (i < NC) ev[i] = v;
        sm += v;
    }
    #pragma unroll
    for (int o = 16; o; o >>= 1) sm += __shfl_xor_sync(0xffffffffu, sm, o);
    float inv = 1.f / (sm + 1e-16f);

    unsigned long long acc2[4] = {0ull, 0ull, 0ull, 0ull};
    int lane4 = lane * 4;
    for (int base = b; base < e; base += 32) {
        int p = base + lane;
        int idx = (base - b) >> 5;
        float aa = 0.f; int cc = 0;
        if (p < e) {
            if (idx < NC) { aa = ev[idx] * inv; cc = col[idx]; }
            else {
                cc = g_col[p];
                float4 sv = ((const float4*)g_as)[cc];
                aa = __expf(lrelu((sv.x + sv.y) + (sv.z + sv.w) + ad) - mx) * inv;
            }
            if (alpha_out) alpha_out[g_eid[p]] = aa;
        }
        stage[wid][lane] = make_float2(aa, __int_as_float(cc * 128));
        __syncwarp();
        int lim = min(32, e - base);
        #pragma unroll 4
        for (int t = 0; t < lim; t++) {
            float2 sc = stage[wid][t];
            unsigned long long ap;
            asm("mov.b64 %0, {%1,%2};" : "=l"(ap) : "f"(sc.x), "f"(sc.x));
            const uint4* hp = (const uint4*)(g_Hb + __float_as_int(sc.y) + lane4);
            uint4 v = *hp;
            ffma2(acc2[0], v.x << 16, v.x & 0xFFFF0000u, ap);
            ffma2(acc2[1], v.y << 16, v.y & 0xFFFF0000u, ap);
            ffma2(acc2[2], v.z << 16, v.z & 0xFFFF0000u, ap);
            ffma2(acc2[3], v.w << 16, v.w & 0xFFFF0000u, ap);
        }
        __syncwarp();
    }
    float acc[8];
    #pragma unroll
    for (int j = 0; j < 4; j++)
        asm("mov.b64 {%0,%1}, %2;" : "=f"(acc[2 * j]), "=f"(acc[2 * j + 1]) : "l"(acc2[j]));
    float4 o0, o1;
    const float4* bv = (const float4*)&bias[lane * 8];
    float4 b0 = bv[0], b1 = bv[1];
    o0.x = geluf(acc[0] + b0.x); o0.y = geluf(acc[1] + b0.y);
    o0.z = geluf(acc[2] + b0.z); o0.w = geluf(acc[3] + b0.w);
    o1.x = geluf(acc[4] + b1.x); o1.y = geluf(acc[5] + b1.y);
    o1.z = geluf(acc[6] + b1.z); o1.w = geluf(acc[7] + b1.w);
    float4* xp = (float4*)&g_X[d * 256 + lane * 8];
    xp[0] = o0; xp[1] = o1;
    if (!last) {
        uint4 xb;
        xb.x = packbf2(o0.x, o0.y); xb.y = packbf2(o0.z, o0.w);
        xb.z = packbf2(o1.x, o1.y); xb.w = packbf2(o1.z, o1.w);
        ((uint4*)&g_Xb[d * 128])[lane] = xb;
    }
}

// ---- pool (blocks 0-15) + MLP head (block 16, spin-wait) --------------------
__global__ void __launch_bounds__(512) k_poolmlp(const float* __restrict__ Wl1, const float* __restrict__ bl1,
                                                 const float* __restrict__ Wl2, const float* __restrict__ bl2,
                                                 const float* __restrict__ Wl3, const float* __restrict__ bl3,
                                                 float* __restrict__ out) {
    int t = threadIdx.x;
    if (blockIdx.x < NGRAPH) {
        __shared__ float sbuf[8][256];
        int g = blockIdx.x;
        int s = t >> 6, c4 = t & 63;
        int b = g_goff[g], e = g_goff[g + 1];
        float4 acc = make_float4(0, 0, 0, 0);
        for (int i = b + s; i < e; i += 8) {
            float4 v = *(const float4*)&g_X[i * 256 + c4 * 4];
            acc.x += v.x; acc.y += v.y; acc.z += v.z; acc.w += v.w;
        }
        *(float4*)&sbuf[s][c4 * 4] = acc;
        __syncthreads();
        if (s == 0) {
            #pragma unroll
            for (int k = 0; k < 4; k++) {
                int c = c4 * 4 + k;
                float v = 0.f;
                #pragma unroll
                for (int r = 0; r < 8; r++) v += sbuf[r][c];
                g_gsum[g * 256 + c] = v;
            }
        }
        __threadfence();
        __syncthreads();
        if (t == 0) atomicAdd(&g_done, 1);
        return;
    }
    if (t == 0) {
        while (atomicAdd(&g_done, 0) < NGRAPH) __nanosleep(200);
    }
    __syncthreads();
    __threadfence();
    __shared__ float G[16 * 256];
    __shared__ float G1[16 * 128];
    __shared__ float G2[16 * 64];
    for (int i = t; i < 4096; i += 512) {
        int g = i >> 8;
        int cnt = g_goff[g + 1] - g_goff[g];
        G[i] = g_gsum[i] / (float)(cnt > 0 ? cnt : 1);
    }
    __syncthreads();
    for (int i = t; i < 2048; i += 512) {
        int gi = i >> 7, j = i & 127;
        float a = bl1[j];
        for (int k = 0; k < 256; k++) a += G[gi * 256 + k] * Wl1[k * 128 + j];
        G1[i] = geluf(a);
    }
    __syncthreads();
    for (int i = t; i < 1024; i += 512) {
        int gi = i >> 6, j = i & 63;
        float a = bl2[j];
        for (int k = 0; k < 128; k++) a += G1[gi * 128 + k] * Wl2[k * 64 + j];
        G2[i] = geluf(a);
    }
    __syncthreads();
    if (t < 16) {
        float a = bl3[0];
        for (int k = 0; k < 64; k++) a += G2[t * 64 + k] * Wl3[k];
        out[t] = 1.f / (1.f + expf(-a));
    }
}

// ---------------- host launcher ------------------------------------------------
extern "C" void kernel_launch(void* const* d_in, const int* in_sizes, int n_in,
                              void* d_out, int out_size) {
    const float* x     = (const float*)d_in[0];
    const void*  ei    = d_in[1];
    const void*  batch = d_in[2];
    const float* W1  = (const float*)d_in[3];
    const float* as1 = (const float*)d_in[4];
    const float* ad1 = (const float*)d_in[5];
    const float* b1  = (const float*)d_in[6];
    const float* W2  = (const float*)d_in[7];
    const float* as2 = (const float*)d_in[8];
    const float* ad2 = (const float*)d_in[9];
    const float* b2  = (const float*)d_in[10];
    const float* Wl1 = (const float*)d_in[11];
    const float* bl1 = (const float*)d_in[12];
    const float* Wl2 = (const float*)d_in[13];
    const float* bl2 = (const float*)d_in[14];
    const float* Wl3 = (const float*)d_in[15];
    const float* bl3 = (const float*)d_in[16];

    int Nn = in_sizes[0];
    int E = in_sizes[1] / 2;
    int Etot = E + Nn;
    float* out = (float*)d_out;
    bool full = (out_size >= 16 + 3 * Etot);
    float* attn_out  = full ? (out + 16) : nullptr;
    float* alpha_out = full ? (out + 16 + 2 * Etot) : nullptr;

    int NBfill = (Etot + 255) / 256;
    int NBf1   = (Nn + 7) / 8;
    int NBgrid = (NBf1 > NBfill) ? NBf1 : NBfill;

    cudaFuncSetAttribute(k_gemm, cudaFuncAttributeMaxDynamicSharedMemorySize, 46080);

    // 1: detect + prep1 + deg count + sd1 + bounds + W2 pack + counter reset
    k_pre<<<(Etot + 255) / 256, 256>>>(ei, x, batch, W1, as1, ad1, W2, E, Etot, Nn);
    // 2: prefix scan (self-cleans g_deg)
    k_scan<<<1, 1024>>>(Nn);
    // 3: CSR fill + attn idx + fused layer 1
    k_fillf1<<<NBgrid, 256>>>(ei, E, Etot, Nn, NBfill, attn_out, x, W1, b1);
    // 4-9: layers 2-4
    for (int l = 0; l < 3; l++) {
        k_gemm<<<dim3((Nn + 127) / 128, 4), 256, 46080>>>(l, as2 + l * 256,
                                                          ad2 + l * 256, Nn);
        k_fatt<<<(Nn + 7) / 8, 256>>>(b2 + l * 256, Nn,
                                      (l == 2) ? alpha_out : nullptr, l == 2);
    }
    // 10: pool + MLP head
    k_poolmlp<<<NGRAPH + 1, 512>>>(Wl1, bl1, Wl2, bl2, Wl3, bl3, out);
}